// round 17
// baseline (speedup 1.0000x reference)
#include <cuda_runtime.h>
#include <cuda_fp16.h>
#include <math_constants.h>
#include <cstdint>

#define D 128
constexpr int NPAD = 20096;   // 157 * 128
constexpr int MPAD = 16384;
constexpr int NCH = 8;        // k-chunks of 16 (single fp16, no split)
constexpr int MSPLIT = 16;
constexpr int CHUNKM = MPAD / MSPLIT;   // 1024
constexpr int MQ = 16;
constexpr int BN = 128;
constexpr int NJB = MPAD / 32;          // 512 j-blocks of 32
constexpr int MAXC = 64;
#define MARGIN 1.0f

// ---------------- device scratch ----------------
static __device__ int g_best[NPAD];
static __device__ unsigned int g_amin[NPAD];             // monotonic-mapped approx row min
static __device__ float g_y2[MPAD];
static __device__ float g_bmin[(size_t)NJB * NPAD];      // [jb][row], 41MB
static __device__ __half g_Ah[(size_t)NCH * NPAD * 16];  // [chunk][row][16]
static __device__ __half g_Bh[(size_t)NCH * MPAD * 16];  // [chunk][j][16]

// ---------------- helpers ----------------
__device__ __forceinline__ uint32_t cvta_shared(const void* p) {
    uint32_t a;
    asm("{ .reg .u64 t; cvta.to.shared.u64 t, %1; cvt.u32.u64 %0, t; }" : "=r"(a) : "l"(p));
    return a;
}
__device__ __forceinline__ void cp16(uint32_t dst, const void* src) {
    asm volatile("cp.async.cg.shared.global [%0], [%1], 16;" :: "r"(dst), "l"(src));
}
#define CP_COMMIT() asm volatile("cp.async.commit_group;" ::: "memory")
#define CP_WAIT(n)  asm volatile("cp.async.wait_group %0;" :: "n"(n) : "memory")
#define LDSM4(r0,r1,r2,r3,addr) \
    asm volatile("ldmatrix.sync.aligned.m8n8.x4.shared.b16 {%0,%1,%2,%3}, [%4];" \
                 : "=r"(r0),"=r"(r1),"=r"(r2),"=r"(r3) : "r"(addr))
#define MMA16816(d0,d1,d2,d3,a0,a1,a2,a3,b0,b1) \
    asm volatile("mma.sync.aligned.m16n8k16.row.col.f32.f16.f16.f32 " \
                 "{%0,%1,%2,%3}, {%4,%5,%6,%7}, {%8,%9}, {%0,%1,%2,%3};" \
                 : "+f"(d0),"+f"(d1),"+f"(d2),"+f"(d3) \
                 : "r"(a0),"r"(a1),"r"(a2),"r"(a3),"r"(b0),"r"(b1))

__device__ __forceinline__ unsigned int fmono(float f) {
    unsigned int u = __float_as_uint(f);
    return (u & 0x80000000u) ? ~u : (u | 0x80000000u);
}
__device__ __forceinline__ float fmono_inv(unsigned int u) {
    return (u & 0x80000000u) ? __uint_as_float(u ^ 0x80000000u) : __uint_as_float(~u);
}

// ---------------- prep ----------------
__global__ void prepA(const float* __restrict__ src, int N) {
    int i = blockIdx.x * blockDim.x + threadIdx.x;
    if (i < NPAD) g_amin[i] = 0xFFFFFFFFu;
    if (i >= NCH * NPAD * 16) return;
    int h = i & 15, row = (i >> 4) % NPAD, c = i / (NPAD * 16);
    __half out = __float2half_rn(0.f);
    if (row < N) out = __float2half_rn(src[row * D + c * 16 + h]);
    g_Ah[i] = out;
}
__global__ void prepB(const float* __restrict__ src, int M) {
    int i = blockIdx.x * blockDim.x + threadIdx.x;
    if (i >= NCH * MPAD * 16) return;
    int h = i & 15, row = (i >> 4) % MPAD, c = i / (MPAD * 16);
    __half out = __float2half_rn(0.f);
    if (row < M) out = __float2half_rn(src[row * D + c * 16 + h]);
    g_Bh[i] = out;
}
__global__ void y2_kernel(const float* __restrict__ B, int M) {
    int j = (blockIdx.x * blockDim.x + threadIdx.x) >> 5;
    int lane = threadIdx.x & 31;
    if (j >= MPAD) return;
    if (j >= M) { if (lane == 0) g_y2[j] = CUDART_INF_F; return; }
    float4 v = ((const float4*)(B + (size_t)j * D))[lane];
    float s = v.x * v.x + v.y * v.y + v.z * v.z + v.w * v.w;
    #pragma unroll
    for (int o = 16; o > 0; o >>= 1) s += __shfl_xor_sync(0xffffffffu, s, o);
    if (lane == 0) g_y2[j] = s;
}

// ---------------- pass 1: approx distance GEMM + 32-j block-min + fused row-min ----------------
// block tile 128x128; 8 warps 2(m)x4(n); warp tile 64x32; 2 CTAs/SM.
// Stage = 4 chunks (K=64) = 16KB; 2 stages/tile; 2-slot ring, distance-1 prefetch.
constexpr int AS_BYTES = NCH * 128 * 32;         // 32768
constexpr int SMEM_BYTES = AS_BYTES + 2 * 16384; // 65536

__global__ __launch_bounds__(256, 2)
void argmin_mma(int N, int M) {
    extern __shared__ char smem[];
    const uint32_t AS = cvta_shared(smem);
    const uint32_t BS = AS + AS_BYTES;

    int tid = threadIdx.x, lane = tid & 31, wid = tid >> 5;
    int warp_m = wid >> 2, warp_n = wid & 3;
    int row0 = blockIdx.x * 128;
    int j0 = blockIdx.y * CHUNKM;
    const int ntiles = CHUNKM / BN;   // 8

    // resident A stripe
    #pragma unroll
    for (int it = 0; it < 8; ++it) {
        int i = it * 256 + tid;
        int c = i >> 8, rem = i & 255, r = rem >> 1, c2 = rem & 1;
        uint4 v = *((const uint4*)(g_Ah + ((size_t)(c * NPAD + row0 + r) << 4)) + c2);
        uint32_t dst = AS + c * 4096 + r * 32 + ((c2 ^ ((r >> 2) & 1)) << 4);
        asm volatile("st.shared.v4.b32 [%0], {%1,%2,%3,%4};"
                     :: "r"(dst), "r"(v.x), "r"(v.y), "r"(v.z), "r"(v.w));
    }

    uint32_t sw16 = (uint32_t)(((lane >> 4) ^ ((lane >> 2) & 1)) << 4);
    uint32_t a_off = (uint32_t)((warp_m * 64 + (lane & 15)) * 32) + sw16;
    uint32_t b_off = (uint32_t)((warp_n * 32 + (lane & 15)) * 32) + sw16;

    // per-thread cp.async coords (4 x 16B per 16KB stage)
    int cp_cl[4], cp_r[4], cp_c2[4]; uint32_t cp_dst[4];
    #pragma unroll
    for (int it = 0; it < 4; ++it) {
        int u = it * 256 + tid;
        int cl = u >> 8, rem = u & 255, r = rem >> 1, c2 = rem & 1;
        cp_cl[it] = cl; cp_r[it] = r; cp_c2[it] = c2;
        cp_dst[it] = cl * 4096 + r * 32 + ((c2 ^ ((r >> 2) & 1)) << 4);
    }

    // prefetch stage 0 into slot 0
    #pragma unroll
    for (int it = 0; it < 4; ++it) {
        const char* src = (const char*)(g_Bh + ((size_t)(cp_cl[it] * MPAD + j0 + cp_r[it]) << 4)) + cp_c2[it] * 16;
        cp16(BS + cp_dst[it], src);
    }
    CP_COMMIT();
    __syncthreads();   // also covers A-stripe stores

    float rmin[4][2];
    #pragma unroll
    for (int mf = 0; mf < 4; ++mf) { rmin[mf][0] = CUDART_INF_F; rmin[mf][1] = CUDART_INF_F; }

    for (int t = 0; t < ntiles; ++t) {
        int jt = j0 + t * BN;
        float d[4][4][4];
        #pragma unroll
        for (int mf = 0; mf < 4; ++mf)
            #pragma unroll
            for (int nf = 0; nf < 4; ++nf)
                #pragma unroll
                for (int c = 0; c < 4; ++c) d[mf][nf][c] = 0.f;

        #pragma unroll 1
        for (int s = 0; s < 2; ++s) {
            int g = t * 2 + s;
            CP_WAIT(0);
            __syncthreads();
            uint32_t slot_base = BS + (uint32_t)(g & 1) * 16384;

            // prefetch next stage into other slot
            {
                int ng = g + 1;
                int nt = ng >> 1, ns = ng & 1;
                if (nt < ntiles) {
                    int njt = j0 + nt * BN;
                    uint32_t ndst = BS + (uint32_t)(ng & 1) * 16384;
                    #pragma unroll
                    for (int it = 0; it < 4; ++it) {
                        const char* src = (const char*)(g_Bh +
                            ((size_t)((4 * ns + cp_cl[it]) * MPAD + njt + cp_r[it]) << 4)) + cp_c2[it] * 16;
                        cp16(ndst + cp_dst[it], src);
                    }
                }
                CP_COMMIT();
            }

            // compute 4 chunks (c = 4s..4s+3)
            #pragma unroll
            for (int cc = 0; cc < 4; ++cc) {
                int c = 4 * s + cc;
                uint32_t b[2][4];
                #pragma unroll
                for (int p = 0; p < 2; ++p)
                    LDSM4(b[p][0], b[p][1], b[p][2], b[p][3],
                          slot_base + cc * 4096 + b_off + p * 512);
                uint32_t a[4][4];
                #pragma unroll
                for (int mf = 0; mf < 4; ++mf)
                    LDSM4(a[mf][0], a[mf][1], a[mf][2], a[mf][3],
                          AS + c * 4096 + a_off + mf * 512);
                #pragma unroll
                for (int mf = 0; mf < 4; ++mf)
                    #pragma unroll
                    for (int nf = 0; nf < 4; ++nf) {
                        int p = nf >> 1, o = nf & 1;
                        MMA16816(d[mf][nf][0], d[mf][nf][1], d[mf][nf][2], d[mf][nf][3],
                                 a[mf][0], a[mf][1], a[mf][2], a[mf][3],
                                 b[p][o], b[p][2 + o]);
                    }
            }
        }

        // epilogue: 32-j block-min + running row-min
        float y2v[8];
        #pragma unroll
        for (int nf = 0; nf < 4; ++nf)
            #pragma unroll
            for (int cl = 0; cl < 2; ++cl)
                y2v[nf * 2 + cl] = __ldg(&g_y2[jt + warp_n * 32 + nf * 8 + ((lane & 3) << 1) + cl]);
        int jb = (jt >> 5) + warp_n;
        #pragma unroll
        for (int mf = 0; mf < 4; ++mf)
            #pragma unroll
            for (int hc = 0; hc < 2; ++hc) {
                float v = CUDART_INF_F;
                #pragma unroll
                for (int nf = 0; nf < 4; ++nf)
                    #pragma unroll
                    for (int cl = 0; cl < 2; ++cl)
                        v = fminf(v, fmaf(-2.f, d[mf][nf][hc * 2 + cl], y2v[nf * 2 + cl]));
                v = fminf(v, __shfl_xor_sync(0xffffffffu, v, 1));
                v = fminf(v, __shfl_xor_sync(0xffffffffu, v, 2));
                rmin[mf][hc] = fminf(rmin[mf][hc], v);
                if ((lane & 3) == 0) {
                    int row = row0 + warp_m * 64 + mf * 16 + hc * 8 + (lane >> 2);
                    g_bmin[(size_t)jb * NPAD + row] = v;
                }
            }
    }

    // fused phase A: one atomic per covered row
    if ((lane & 3) == 0) {
        #pragma unroll
        for (int mf = 0; mf < 4; ++mf)
            #pragma unroll
            for (int hc = 0; hc < 2; ++hc) {
                int row = row0 + warp_m * 64 + mf * 16 + hc * 8 + (lane >> 2);
                atomicMin(&g_amin[row], fmono(rmin[mf][hc]));
            }
    }
}

// ---------------- pass 2: exact refine over candidate 32-j blocks ----------------
__global__ __launch_bounds__(256)
void refine_kernel(const float* __restrict__ clear, const float* __restrict__ rain,
                   int N, int M) {
    __shared__ int   cnt[32];
    __shared__ unsigned short cand[32][MAXC];
    __shared__ float xs[8][D];
    int tid = threadIdx.x, lane = tid & 31, wid = tid >> 5;
    int row0 = blockIdx.x * 32;
    int row = row0 + lane;
    int jb0 = wid * (NJB / 8);

    if (wid == 0) cnt[lane] = 0;
    __syncthreads();

    // collect candidate jb's (threshold from fused pass-1 row min)
    float tr = fmono_inv(g_amin[row]) + MARGIN;
    for (int jb = jb0; jb < jb0 + NJB / 8; ++jb) {
        if (g_bmin[(size_t)jb * NPAD + row] <= tr) {
            int p = atomicAdd(&cnt[lane], 1);
            if (p < MAXC) cand[lane][p] = (unsigned short)jb;
        }
    }
    __syncthreads();

    // warp w refines rows w*4 .. w*4+3 exactly (fp32), 32 j per candidate block
    for (int q = 0; q < 4; ++q) {
        int rl = wid * 4 + q;
        int r = row0 + rl;
        if (r >= N) continue;
        #pragma unroll
        for (int i = 0; i < 4; ++i)
            xs[wid][lane * 4 + i] = clear[(size_t)r * D + lane * 4 + i];
        __syncwarp();
        int nc = min(cnt[rl], MAXC);
        float bd = CUDART_INF_F; int bj = 0x7FFFFFFF;
        for (int ci = 0; ci < nc; ++ci) {
            int jb = cand[rl][ci];
            int j = jb * 32 + lane;
            float dist = CUDART_INF_F;
            if (j < M) {
                const float4* y4 = (const float4*)(rain + (size_t)j * D);
                const float4* x4 = (const float4*)xs[wid];
                float acc = 0.f;
                #pragma unroll
                for (int k = 0; k < D / 4; ++k) {
                    float4 yv = y4[k], xv = x4[k];
                    acc += xv.x * yv.x + xv.y * yv.y + xv.z * yv.z + xv.w * yv.w;
                }
                dist = g_y2[j] - 2.f * acc;
            }
            if (dist < bd || (dist == bd && j < bj)) { bd = dist; bj = j; }
        }
        #pragma unroll
        for (int off = 16; off > 0; off >>= 1) {
            float od = __shfl_xor_sync(0xffffffffu, bd, off);
            int oj = __shfl_xor_sync(0xffffffffu, bj, off);
            if (od < bd || (od == bd && oj < bj)) { bd = od; bj = oj; }
        }
        if (lane == 0) g_best[r] = bj;
        __syncwarp();
    }
}

// ---------------- MLP + gated fusion (16 queries / block) ----------------
__global__ __launch_bounds__(128)
void mlp_kernel(const float* __restrict__ clear, const float* __restrict__ rain,
                const float* __restrict__ W1, const float* __restrict__ b1,
                const float* __restrict__ W2, const float* __restrict__ b2,
                float* __restrict__ out, int N) {
    __shared__ float cs[MQ][D], als[MQ][D];
    __shared__ float hred[MQ][4];
    int q0 = blockIdx.x * MQ;
    int d = threadIdx.x;
    #pragma unroll
    for (int q = 0; q < MQ; ++q) {
        int row = q0 + q; if (row >= N) row = N - 1;
        cs[q][d] = clear[(size_t)row * D + d];
        int idx = g_best[row];
        als[q][d] = rain[(size_t)idx * D + d];
    }
    __syncthreads();

    float h[MQ];
    float bb = b1[d];
    #pragma unroll
    for (int q = 0; q < MQ; ++q) h[q] = bb;

    const float4* w4 = (const float4*)(W1 + (size_t)d * (2 * D));
    #pragma unroll 4
    for (int k = 0; k < D / 4; ++k) {
        float4 w = w4[k];
        #pragma unroll
        for (int q = 0; q < MQ; ++q) {
            float4 c = *(const float4*)&cs[q][k * 4];
            h[q] += w.x * c.x + w.y * c.y + w.z * c.z + w.w * c.w;
        }
    }
    #pragma unroll 4
    for (int k = 0; k < D / 4; ++k) {
        float4 w = w4[D / 4 + k];
        #pragma unroll
        for (int q = 0; q < MQ; ++q) {
            float4 c = *(const float4*)&als[q][k * 4];
            h[q] += w.x * c.x + w.y * c.y + w.z * c.z + w.w * c.w;
        }
    }
    float w2d = W2[d];
    #pragma unroll
    for (int q = 0; q < MQ; ++q) {
        float p = fmaxf(h[q], 0.f) * w2d;
        #pragma unroll
        for (int o = 16; o > 0; o >>= 1) p += __shfl_xor_sync(0xffffffffu, p, o);
        if ((d & 31) == 0) hred[q][d >> 5] = p;
    }
    __syncthreads();
    float bias2 = b2[0];
    #pragma unroll
    for (int q = 0; q < MQ; ++q) {
        int row = q0 + q;
        if (row < N) {
            float s = hred[q][0] + hred[q][1] + hred[q][2] + hred[q][3] + bias2;
            float wq = 1.f / (1.f + __expf(-s));
            out[(size_t)row * D + d] = wq * cs[q][d] + (1.f - wq) * als[q][d];
        }
    }
}

extern "C" void kernel_launch(void* const* d_in, const int* in_sizes, int n_in,
                              void* d_out, int out_size) {
    const float* clear = (const float*)d_in[0];
    const float* rain  = (const float*)d_in[1];
    const float* W1    = (const float*)d_in[2];
    const float* b1    = (const float*)d_in[3];
    const float* W2    = (const float*)d_in[4];
    const float* b2    = (const float*)d_in[5];
    float* out = (float*)d_out;
    int N = in_sizes[0] / D;
    int M = in_sizes[1] / D;

    cudaFuncSetAttribute(argmin_mma, cudaFuncAttributeMaxDynamicSharedMemorySize, SMEM_BYTES);

    int nA = NCH * NPAD * 16, nB = NCH * MPAD * 16;
    prepA<<<(nA + 255) / 256, 256>>>(clear, N);            // launch 0 (inits g_amin)
    prepB<<<(nB + 255) / 256, 256>>>(rain, M);             // launch 1
    y2_kernel<<<(MPAD * 32 + 255) / 256, 256>>>(rain, M);  // launch 2

    dim3 grid((N + 127) / 128, MSPLIT);
    argmin_mma<<<grid, 256, SMEM_BYTES>>>(N, M);           // launch 3 -> profiled slot

    refine_kernel<<<NPAD / 32, 256>>>(clear, rain, N, M);  // launch 4
    mlp_kernel<<<(N + MQ - 1) / MQ, 128>>>(clear, rain, W1, b1, W2, b2, out, N);
}